// round 16
// baseline (speedup 1.0000x reference)
#include <cuda_runtime.h>
#include <cuda_fp16.h>
#include <math.h>
#include <stdint.h>

#define B_   128
#define P_   196
#define E_   2048
#define A_   512
#define M_   (B_ * P_)   // 25088

// ---------------- scratch (__device__ globals; no allocs) ----------------
__device__ __align__(16) __half g_WH[(size_t)E_ * A_];   // W_enc fp16 [E,A]
__device__ float g_att2p[4 * B_ * A_];      // att2 d-chunk partials
__device__ float g_part[4 * M_];            // per-(n-block) partial scores
__device__ float g_wpart[4 * B_ * E_];      // weighted-sum p-split partials

// ---------------- small helpers ----------------
__device__ __forceinline__ uint32_t smem_u32(const void* p) {
    uint32_t a;
    asm("{ .reg .u64 t; cvta.to.shared.u64 t, %1; cvt.u32.u64 %0, t; }"
        : "=r"(a) : "l"(p));
    return a;
}
__device__ __forceinline__ void cp16(uint32_t dst, const void* src) {
    asm volatile("cp.async.cg.shared.global [%0], [%1], 16;"
                 :: "r"(dst), "l"(src) : "memory");
}
__device__ __forceinline__ void cp_commit() {
    asm volatile("cp.async.commit_group;" ::: "memory");
}
__device__ __forceinline__ void cp_wait1() {
    asm volatile("cp.async.wait_group 1;" ::: "memory");
}
__device__ __forceinline__ void ldsm_x4(uint32_t* r, uint32_t addr) {
    asm volatile("ldmatrix.sync.aligned.m8n8.x4.shared.b16 {%0,%1,%2,%3}, [%4];"
                 : "=r"(r[0]), "=r"(r[1]), "=r"(r[2]), "=r"(r[3]) : "r"(addr));
}
__device__ __forceinline__ void ldsm_x4_t(uint32_t* r, uint32_t addr) {
    asm volatile("ldmatrix.sync.aligned.m8n8.x4.trans.shared.b16 {%0,%1,%2,%3}, [%4];"
                 : "=r"(r[0]), "=r"(r[1]), "=r"(r[2]), "=r"(r[3]) : "r"(addr));
}
__device__ __forceinline__ void mma_fp16(float* c, const uint32_t* a,
                                         uint32_t b0, uint32_t b1) {
    asm volatile(
        "mma.sync.aligned.m16n8k16.row.col.f32.f16.f16.f32 "
        "{%0,%1,%2,%3}, {%4,%5,%6,%7}, {%8,%9}, {%0,%1,%2,%3};"
        : "+f"(c[0]), "+f"(c[1]), "+f"(c[2]), "+f"(c[3])
        : "r"(a[0]), "r"(a[1]), "r"(a[2]), "r"(a[3]), "r"(b0), "r"(b1));
}
__device__ __forceinline__ uint32_t pack_h2(__half x, __half y) {
    __half2 t = __halves2half2(x, y);   // x -> low 16 bits
    return *reinterpret_cast<uint32_t*>(&t);
}
// packed fp32x2 -> fp16x2 (lo -> low 16 bits), same rn rounding as __float2half_rn
__device__ __forceinline__ uint32_t cvt_h2(float lo, float hi) {
    uint32_t r;
    asm("cvt.rn.f16x2.f32 %0, %1, %2;" : "=r"(r) : "f"(hi), "f"(lo));
    return r;
}
__device__ __forceinline__ void sts64(uint32_t a, uint32_t x, uint32_t y) {
    asm volatile("st.shared.v2.b32 [%0], {%1, %2};"
                 :: "r"(a), "r"(x), "r"(y) : "memory");
}

// ---------------------------------------------------------------------------
// Kernel A: fp32 -> fp16 round for W_enc only (1MB, ~2us)
// ---------------------------------------------------------------------------
__global__ void round_kernel(const float* __restrict__ in,
                             __half* __restrict__ out, int n4) {
    int i = blockIdx.x * 256 + threadIdx.x;
    if (i >= n4) return;
    float4 v = reinterpret_cast<const float4*>(in)[i];
    reinterpret_cast<uint2*>(out)[i] = make_uint2(
        pack_h2(__float2half_rn(v.x), __float2half_rn(v.y)),
        pack_h2(__float2half_rn(v.z), __float2half_rn(v.w)));
}

// ---------------------------------------------------------------------------
// Kernel B: att2 partials, 2-D split (batch-group x d-chunk). (round-15 WIN)
// grid=(32, 4) = 128 CTAs, block=512.
// ---------------------------------------------------------------------------
#define A2GB    4          // batches per CTA
#define DSPLIT  4
#define DCHUNK  (A_ / DSPLIT)   // 128

__global__ void att2_kernel(const float* __restrict__ dh,
                            const float* __restrict__ Wd,
                            float* __restrict__ att2p) {
    __shared__ float h[A2GB][DCHUNK];
    const int tid = threadIdx.x;           // 0..511
    const int b0  = blockIdx.x * A2GB;
    const int z   = blockIdx.y;
    const int d0  = z * DCHUNK;

    h[tid >> 7][tid & 127] = dh[(b0 + (tid >> 7)) * A_ + d0 + (tid & 127)];
    __syncthreads();

    const int a = tid;
    float acc[A2GB] = {0.f, 0.f, 0.f, 0.f};
#pragma unroll 8
    for (int d = 0; d < DCHUNK; d++) {
        const float w = __ldg(Wd + (size_t)(d0 + d) * A_ + a);
#pragma unroll
        for (int g = 0; g < A2GB; g++)
            acc[g] = fmaf(h[g][d], w, acc[g]);
    }
#pragma unroll
    for (int g = 0; g < A2GB; g++)
        att2p[((size_t)z * B_ + b0 + g) * A_ + a] = acc[g];
}

// ---------------------------------------------------------------------------
// Kernel C: fp16 mma.sync GEMM, A converted fp32->fp16 IN-KERNEL, BK=64.
// CTA 128x128, 8 warps (2Mx4N), warp tile 64x32, 3-stage B ring, 32 chunks.
// grid=(4,196), block=256
// ---------------------------------------------------------------------------
#define BK         64
#define NKCH       (E_ / BK)        // 32
#define A_STRIDE   144              // 128B data + 16B pad (ldsm conflict-free)
#define B_STRIDE   272              // 256B data + 16B pad
#define AS_SZ      (128 * A_STRIDE) // 18432
#define BS_OFF     AS_SZ
#define STAGE      (AS_SZ + 64 * B_STRIDE)     // 35840
#define NSTAGE     3
#define EPI_OFF    (NSTAGE * STAGE)            // 107520
#define SMEM_TOT   (EPI_OFF + 3 * 128 * 4)     // 109056

__global__ __launch_bounds__(256, 2)
void gemm_score_kernel(const float* __restrict__ enc,
                       const __half* __restrict__ WH,
                       const float* __restrict__ bEnc,
                       const float* __restrict__ att2p,
                       const float* __restrict__ bd,
                       const float* __restrict__ Wf,
                       float* __restrict__ part) {
    extern __shared__ char smem[];
    const uint32_t sb = smem_u32(smem);
    const int tid  = threadIdx.x;
    const int lane = tid & 31;
    const int wid  = tid >> 5;
    const int warpM = wid >> 2;          // 0..1
    const int warpN = wid & 3;           // 0..3
    const int m0 = blockIdx.y * 128;
    const int n0 = blockIdx.x * 128;

    float* sum0 = (float*)(smem + EPI_OFF);
    float* sum1 = sum0 + 128;
    float* swf  = sum1 + 128;
    const int b0 = m0 / P_;
    const int rowsplit = (b0 + 1) * P_ - m0;   // rows >= this use batch b0+1
    if (tid < 128) {
        const int b1 = (b0 + 1 < B_) ? b0 + 1 : B_ - 1;
        const int col = n0 + tid;
        const float base = bEnc[col] + bd[col];
        const size_t s = (size_t)B_ * A_;
        const float* p0 = att2p + (size_t)b0 * A_ + col;
        const float* p1 = att2p + (size_t)b1 * A_ + col;
        sum0[tid] = base + ((p0[0] + p0[s]) + (p0[2 * s] + p0[3 * s]));
        sum1[tid] = base + ((p1[0] + p1[s]) + (p1[2 * s] + p1[3 * s]));
        swf[tid]  = Wf[col];
    }

    float acc[4][4][4];
#pragma unroll
    for (int i = 0; i < 4; i++)
#pragma unroll
        for (int j = 0; j < 4; j++)
#pragma unroll
            for (int q = 0; q < 4; q++) acc[i][j][q] = 0.f;

    // per-thread A mapping: 8 float4; row = (tid>>4)+16*i, f4-col = tid&15
    const int ar = tid >> 4;            // 0..15
    const int aq = tid & 15;            // 0..15

    float4 abuf[8];                     // A fp32 reg buffer (one chunk ahead)

    auto ldgA = [&](int kc) {
        const float* base = enc + (size_t)m0 * E_ + kc * BK;
#pragma unroll
        for (int i = 0; i < 8; i++) {
            int r = ar + 16 * i;
            abuf[i] = __ldg((const float4*)(base + (size_t)r * E_) + aq);
        }
    };
    auto cvtA = [&](int st) {
        const uint32_t sbase = sb + st * STAGE;
#pragma unroll
        for (int i = 0; i < 8; i++) {
            int r = ar + 16 * i;
            sts64(sbase + (uint32_t)(r * A_STRIDE + aq * 8),
                  cvt_h2(abuf[i].x, abuf[i].y), cvt_h2(abuf[i].z, abuf[i].w));
        }
    };
    auto loadB = [&](int st, int kc) {
        const uint32_t sbase = sb + st * STAGE + BS_OFF;
        const int k0 = kc * BK;
#pragma unroll
        for (int i = 0; i < 4; i++) {
            int idx = tid + i * 256;               // 0..1023
            int k = idx >> 4, q = idx & 15;        // 64 rows x 16 chunks of 16B
            size_t go = (size_t)(k0 + k) * A_ + n0 + q * 8;
            cp16(sbase + (uint32_t)(k * B_STRIDE + q * 16), WH + go);
        }
    };

    // prologue
    ldgA(0);
    loadB(0, 0); cp_commit();
    loadB(1, 1); cp_commit();
    cvtA(0);        // A chunk 0 -> stage 0
    ldgA(1);        // prefetch A chunk 1

    // ldmatrix lane addressing
    const uint32_t a_row  = (uint32_t)(warpM * 64 + (lane & 15));
    const uint32_t a_colb = (uint32_t)((lane >> 4) * 16);
    const uint32_t b_krow = (uint32_t)(((lane >> 3) & 1) * 8 + (lane & 7));
    const uint32_t b_colb = (uint32_t)((warpN * 32 + (lane >> 4) * 8) * 2);

    for (int c = 0; c < NKCH; ++c) {
        cp_wait1();
        __syncthreads();     // A-stage c visibility (STS in iter c-1) + WAR
        if (c + 2 < NKCH) loadB((c + 2) % NSTAGE, c + 2);
        cp_commit();
        if (c + 1 < NKCH) cvtA((c + 1) % NSTAGE);   // abuf holds chunk c+1
        if (c + 2 < NKCH) ldgA(c + 2);              // refill abuf

        const uint32_t sbase = sb + (c % NSTAGE) * STAGE;
#pragma unroll
        for (int kk = 0; kk < BK; kk += 16) {
            uint32_t aF[4][4], bF[2][4];
#pragma unroll
            for (int mf = 0; mf < 4; mf++) {
                uint32_t ad = sbase + (a_row + mf * 16) * A_STRIDE + kk * 2 + a_colb;
                ldsm_x4(aF[mf], ad);
            }
#pragma unroll
            for (int np = 0; np < 2; np++) {
                uint32_t bdx = sbase + BS_OFF + (b_krow + kk) * B_STRIDE + b_colb + np * 32;
                ldsm_x4_t(bF[np], bdx);
            }
#pragma unroll
            for (int mf = 0; mf < 4; mf++)
#pragma unroll
                for (int nt = 0; nt < 4; nt++) {
                    const int np = nt >> 1, hh = (nt & 1) * 2;
                    mma_fp16(acc[mf][nt], aF[mf], bF[np][hh], bF[np][hh + 1]);
                }
        }
    }

    // ---- fused score epilogue (deterministic partials) ----
    float* spart = (float*)smem;   // stage smem free now
    __syncthreads();

#pragma unroll
    for (int mf = 0; mf < 4; mf++)
#pragma unroll
        for (int h = 0; h < 2; h++) {
            const int row = warpM * 64 + mf * 16 + (lane >> 2) + h * 8;
            const float* sm = (row >= rowsplit) ? sum1 : sum0;
            float s = 0.f;
#pragma unroll
            for (int nf = 0; nf < 4; nf++)
#pragma unroll
                for (int j = 0; j < 2; j++) {
                    const int col = warpN * 32 + nf * 8 + (lane & 3) * 2 + j;
                    float v = acc[mf][nf][h * 2 + j] + sm[col];
                    s += fmaxf(v, 0.f) * swf[col];
                }
            s += __shfl_xor_sync(0xffffffffu, s, 1);
            s += __shfl_xor_sync(0xffffffffu, s, 2);
            if ((lane & 3) == 0) spart[warpN * 128 + row] = s;
        }
    __syncthreads();
    if (tid < 128) {
        float s = spart[tid] + spart[128 + tid] + spart[256 + tid] + spart[384 + tid];
        part[(size_t)blockIdx.x * M_ + m0 + tid] = s;
    }
}

// ---------------------------------------------------------------------------
// Kernel E: weighted sum with FUSED softmax (round-14 proven).
// grid=(4, 128, 4) z = p-quarter (49 pixels); block=128.
// ---------------------------------------------------------------------------
#define PSPLIT 4
#define PCHUNK 49            // 196 / 4

__global__ void weighted_kernel(const float* __restrict__ part,
                                const float* __restrict__ enc,
                                float* __restrict__ alpha_out,
                                float* __restrict__ wpart) {
    __shared__ float al[P_];
    __shared__ float red[128];
    const int b   = blockIdx.y;
    const int z   = blockIdx.z;
    const int tid = threadIdx.x;

    // ---- in-block softmax over P=196 (deterministic, same in all blocks) ----
    const int m0i = b * P_ + tid;
    float v0 = part[m0i] + part[M_ + m0i] + part[2 * M_ + m0i] + part[3 * M_ + m0i];
    float v1 = -INFINITY;
    if (tid + 128 < P_) {
        const int m1i = m0i + 128;
        v1 = part[m1i] + part[M_ + m1i] + part[2 * M_ + m1i] + part[3 * M_ + m1i];
    }
    red[tid] = fmaxf(v0, v1);
    __syncthreads();
#pragma unroll
    for (int s = 64; s; s >>= 1) {
        if (tid < s) red[tid] = fmaxf(red[tid], red[tid + s]);
        __syncthreads();
    }
    const float mx = red[0];
    __syncthreads();
    float e0 = expf(v0 - mx);
    float e1 = (tid + 128 < P_) ? expf(v1 - mx) : 0.f;
    red[tid] = e0 + e1;
    __syncthreads();
#pragma unroll
    for (int s = 64; s; s >>= 1) {
        if (tid < s) red[tid] += red[tid + s];
        __syncthreads();
    }
    const float inv = 1.f / red[0];
    al[tid] = e0 * inv;
    if (tid + 128 < P_) al[tid + 128] = e1 * inv;
    __syncthreads();

    if (blockIdx.x == 0 && z == 0) {
        alpha_out[b * P_ + tid] = al[tid];
        if (tid + 128 < P_) alpha_out[b * P_ + tid + 128] = al[tid + 128];
    }

    // ---- weighted partial sum over this p-quarter ----
    const int p0 = z * PCHUNK;
    const int e4 = blockIdx.x * 128 + tid;
    const float4* base = (const float4*)(enc + ((size_t)b * P_ + p0) * E_) + e4;
    float4 acc = make_float4(0.f, 0.f, 0.f, 0.f);
#pragma unroll 7
    for (int p = 0; p < PCHUNK; p++) {
        float4 v = __ldg(base + (size_t)p * (E_ / 4));
        float a = al[p0 + p];
        acc.x = fmaf(v.x, a, acc.x);
        acc.y = fmaf(v.y, a, acc.y);
        acc.z = fmaf(v.z, a, acc.z);
        acc.w = fmaf(v.w, a, acc.w);
    }
    ((float4*)(wpart + ((size_t)z * B_ + b) * E_))[e4] = acc;
}

// Kernel F: combine 4 p-partials -> awe.  grid=256, block=256 (float4 each)
__global__ void wcombine_kernel(const float* __restrict__ wpart,
                                float* __restrict__ out) {
    const int i = blockIdx.x * 256 + threadIdx.x;     // float4 idx, B_*E_/4
    const float4* p0 = (const float4*)wpart;
    const float4* p1 = p0 + (size_t)B_ * E_ / 4;
    const float4* p2 = p1 + (size_t)B_ * E_ / 4;
    const float4* p3 = p2 + (size_t)B_ * E_ / 4;
    float4 a = p0[i], b = p1[i], c = p2[i], d = p3[i];
    float4 r;
    r.x = (a.x + b.x) + (c.x + d.x);
    r.y = (a.y + b.y) + (c.y + d.y);
    r.z = (a.z + b.z) + (c.z + d.z);
    r.w = (a.w + b.w) + (c.w + d.w);
    ((float4*)out)[i] = r;
}

// ---------------------------------------------------------------------------
// Launch.  Inputs: encoder_out, decoder_hidden, W_enc, b_enc, W_dec, b_dec,
//                  W_full, b_full.   Output: [awe 128*2048][alpha 128*196]
// ---------------------------------------------------------------------------
extern "C" void kernel_launch(void* const* d_in, const int* in_sizes, int n_in,
                              void* d_out, int out_size) {
    const float* enc   = (const float*)d_in[0];
    const float* dh    = (const float*)d_in[1];
    const float* W_enc = (const float*)d_in[2];
    const float* b_enc = (const float*)d_in[3];
    const float* W_dec = (const float*)d_in[4];
    const float* b_dec = (const float*)d_in[5];
    const float* W_ful = (const float*)d_in[6];

    float* out   = (float*)d_out;
    float* awe   = out;
    float* alpha = out + (size_t)B_ * E_;

    __half* WH;
    float *att2p, *part, *wpart;
    cudaGetSymbolAddress((void**)&WH,     g_WH);
    cudaGetSymbolAddress((void**)&att2p,  g_att2p);
    cudaGetSymbolAddress((void**)&part,   g_part);
    cudaGetSymbolAddress((void**)&wpart,  g_wpart);

    cudaFuncSetAttribute(gemm_score_kernel,
                         cudaFuncAttributeMaxDynamicSharedMemorySize, SMEM_TOT);

    // 1. round W_enc to fp16
    round_kernel<<<(E_ * A_ / 4 + 255) / 256, 256>>>(W_enc, WH, E_ * A_ / 4);

    // 2. att2 partials (2-D split: 128 CTAs, 32MB W_dec traffic)
    att2_kernel<<<dim3(B_ / A2GB, DSPLIT), A_>>>(dh, W_dec, att2p);

    // 3. tensor-core GEMM (fused A-convert, BK=64) + fused score partials
    gemm_score_kernel<<<dim3(4, 196), 256, SMEM_TOT>>>(
        enc, WH, b_enc, att2p, b_dec, W_ful, part);

    // 4. weighted encoding with fused softmax (p-split x4) + combine
    weighted_kernel<<<dim3(4, B_, PSPLIT), 128>>>(part, enc, alpha, wpart);
    wcombine_kernel<<<B_ * E_ / 4 / 256, 256>>>(wpart, awe);
}

// round 17
// speedup vs baseline: 1.1265x; 1.1265x over previous
#include <cuda_runtime.h>
#include <cuda_fp16.h>
#include <math.h>
#include <stdint.h>

#define B_   128
#define P_   196
#define E_   2048
#define A_   512
#define M_   (B_ * P_)   // 25088

// ---------------- scratch (__device__ globals; no allocs) ----------------
__device__ __align__(16) __half g_WH[(size_t)E_ * A_];   // W_enc fp16 [E,A]
__device__ float g_att2p[4 * B_ * A_];      // att2 d-chunk partials
__device__ float g_part[4 * M_];            // per-(n-block) partial scores
__device__ float g_wpart[4 * B_ * E_];      // weighted-sum p-split partials

// ---------------- small helpers ----------------
__device__ __forceinline__ uint32_t smem_u32(const void* p) {
    uint32_t a;
    asm("{ .reg .u64 t; cvta.to.shared.u64 t, %1; cvt.u32.u64 %0, t; }"
        : "=r"(a) : "l"(p));
    return a;
}
__device__ __forceinline__ void cp16(uint32_t dst, const void* src) {
    asm volatile("cp.async.cg.shared.global [%0], [%1], 16;"
                 :: "r"(dst), "l"(src) : "memory");
}
__device__ __forceinline__ void cp_commit() {
    asm volatile("cp.async.commit_group;" ::: "memory");
}
__device__ __forceinline__ void cp_wait2() {
    asm volatile("cp.async.wait_group 2;" ::: "memory");
}
__device__ __forceinline__ void ldsm_x4(uint32_t* r, uint32_t addr) {
    asm volatile("ldmatrix.sync.aligned.m8n8.x4.shared.b16 {%0,%1,%2,%3}, [%4];"
                 : "=r"(r[0]), "=r"(r[1]), "=r"(r[2]), "=r"(r[3]) : "r"(addr));
}
__device__ __forceinline__ void ldsm_x4_t(uint32_t* r, uint32_t addr) {
    asm volatile("ldmatrix.sync.aligned.m8n8.x4.trans.shared.b16 {%0,%1,%2,%3}, [%4];"
                 : "=r"(r[0]), "=r"(r[1]), "=r"(r[2]), "=r"(r[3]) : "r"(addr));
}
__device__ __forceinline__ void mma_fp16(float* c, const uint32_t* a,
                                         uint32_t b0, uint32_t b1) {
    asm volatile(
        "mma.sync.aligned.m16n8k16.row.col.f32.f16.f16.f32 "
        "{%0,%1,%2,%3}, {%4,%5,%6,%7}, {%8,%9}, {%0,%1,%2,%3};"
        : "+f"(c[0]), "+f"(c[1]), "+f"(c[2]), "+f"(c[3])
        : "r"(a[0]), "r"(a[1]), "r"(a[2]), "r"(a[3]), "r"(b0), "r"(b1));
}
__device__ __forceinline__ uint32_t pack_h2(__half x, __half y) {
    __half2 t = __halves2half2(x, y);   // x -> low 16 bits
    return *reinterpret_cast<uint32_t*>(&t);
}
// packed fp32x2 -> fp16x2 (lo -> low 16 bits), same rn rounding as __float2half_rn
__device__ __forceinline__ uint32_t cvt_h2(float lo, float hi) {
    uint32_t r;
    asm("cvt.rn.f16x2.f32 %0, %1, %2;" : "=r"(r) : "f"(hi), "f"(lo));
    return r;
}
__device__ __forceinline__ void sts64(uint32_t a, uint32_t x, uint32_t y) {
    asm volatile("st.shared.v2.b32 [%0], {%1, %2};"
                 :: "r"(a), "r"(x), "r"(y) : "memory");
}

// ---------------------------------------------------------------------------
// Kernel A: fp32 -> fp16 round for W_enc only (1MB, ~2us)
// ---------------------------------------------------------------------------
__global__ void round_kernel(const float* __restrict__ in,
                             __half* __restrict__ out, int n4) {
    int i = blockIdx.x * 256 + threadIdx.x;
    if (i >= n4) return;
    float4 v = reinterpret_cast<const float4*>(in)[i];
    reinterpret_cast<uint2*>(out)[i] = make_uint2(
        pack_h2(__float2half_rn(v.x), __float2half_rn(v.y)),
        pack_h2(__float2half_rn(v.z), __float2half_rn(v.w)));
}

// ---------------------------------------------------------------------------
// Kernel B: att2 partials, 2-D split (batch-group x d-chunk). (round-15 WIN)
// grid=(32, 4) = 128 CTAs, block=512.
// ---------------------------------------------------------------------------
#define A2GB    4          // batches per CTA
#define DSPLIT  4
#define DCHUNK  (A_ / DSPLIT)   // 128

__global__ void att2_kernel(const float* __restrict__ dh,
                            const float* __restrict__ Wd,
                            float* __restrict__ att2p) {
    __shared__ float h[A2GB][DCHUNK];
    const int tid = threadIdx.x;           // 0..511
    const int b0  = blockIdx.x * A2GB;
    const int z   = blockIdx.y;
    const int d0  = z * DCHUNK;

    h[tid >> 7][tid & 127] = dh[(b0 + (tid >> 7)) * A_ + d0 + (tid & 127)];
    __syncthreads();

    const int a = tid;
    float acc[A2GB] = {0.f, 0.f, 0.f, 0.f};
#pragma unroll 8
    for (int d = 0; d < DCHUNK; d++) {
        const float w = __ldg(Wd + (size_t)(d0 + d) * A_ + a);
#pragma unroll
        for (int g = 0; g < A2GB; g++)
            acc[g] = fmaf(h[g][d], w, acc[g]);
    }
#pragma unroll
    for (int g = 0; g < A2GB; g++)
        att2p[((size_t)z * B_ + b0 + g) * A_ + a] = acc[g];
}

// ---------------------------------------------------------------------------
// Kernel C: fp16 mma.sync GEMM, A converted fp32->fp16 IN-KERNEL, BK=32,
// 4-stage cp.async ring (wait_group 2, prefetch distance 3).
// CTA 128x128, 8 warps (2Mx4N), warp tile 64x32. grid=(4,196), block=256
// ---------------------------------------------------------------------------
#define BK         32
#define NKCH       (E_ / BK)        // 64
#define A_STRIDE   80               // 64B data + 16B pad (ldsm conflict-free)
#define B_STRIDE   272              // 256B data + 16B pad
#define AS_SZ      (128 * A_STRIDE) // 10240
#define BS_OFF     AS_SZ
#define STAGE      (AS_SZ + 32 * B_STRIDE)     // 18944
#define NSTAGE     4
#define EPI_OFF    (NSTAGE * STAGE)            // 75776
#define SMEM_TOT   (EPI_OFF + 3 * 128 * 4)     // 77312

__global__ __launch_bounds__(256, 2)
void gemm_score_kernel(const float* __restrict__ enc,
                       const __half* __restrict__ WH,
                       const float* __restrict__ bEnc,
                       const float* __restrict__ att2p,
                       const float* __restrict__ bd,
                       const float* __restrict__ Wf,
                       float* __restrict__ part) {
    extern __shared__ char smem[];
    const uint32_t sb = smem_u32(smem);
    const int tid  = threadIdx.x;
    const int lane = tid & 31;
    const int wid  = tid >> 5;
    const int warpM = wid >> 2;          // 0..1
    const int warpN = wid & 3;           // 0..3
    const int m0 = blockIdx.y * 128;
    const int n0 = blockIdx.x * 128;

    float* sum0 = (float*)(smem + EPI_OFF);
    float* sum1 = sum0 + 128;
    float* swf  = sum1 + 128;
    const int b0 = m0 / P_;
    const int rowsplit = (b0 + 1) * P_ - m0;   // rows >= this use batch b0+1
    if (tid < 128) {
        const int b1 = (b0 + 1 < B_) ? b0 + 1 : B_ - 1;
        const int col = n0 + tid;
        const float base = bEnc[col] + bd[col];
        const size_t s = (size_t)B_ * A_;
        const float* p0 = att2p + (size_t)b0 * A_ + col;
        const float* p1 = att2p + (size_t)b1 * A_ + col;
        sum0[tid] = base + ((p0[0] + p0[s]) + (p0[2 * s] + p0[3 * s]));
        sum1[tid] = base + ((p1[0] + p1[s]) + (p1[2 * s] + p1[3 * s]));
        swf[tid]  = Wf[col];
    }

    float acc[4][4][4];
#pragma unroll
    for (int i = 0; i < 4; i++)
#pragma unroll
        for (int j = 0; j < 4; j++)
#pragma unroll
            for (int q = 0; q < 4; q++) acc[i][j][q] = 0.f;

    // per-thread A mapping: 4 float4 = rows tid>>3 (+32*i), float4-col tid&7
    const int ar = tid >> 3;            // 0..31
    const int aq = tid & 7;             // 0..7

    float4 abuf[4];                     // A fp32 reg buffer (one chunk ahead)

    auto ldgA = [&](int kc) {
        const float* base = enc + (size_t)m0 * E_ + kc * BK;
#pragma unroll
        for (int i = 0; i < 4; i++) {
            int r = ar + 32 * i;
            abuf[i] = __ldg((const float4*)(base + (size_t)r * E_) + aq);
        }
    };
    auto cvtA = [&](int st) {
        const uint32_t sbase = sb + st * STAGE;
#pragma unroll
        for (int i = 0; i < 4; i++) {
            int r = ar + 32 * i;
            sts64(sbase + (uint32_t)(r * A_STRIDE + aq * 8),
                  cvt_h2(abuf[i].x, abuf[i].y), cvt_h2(abuf[i].z, abuf[i].w));
        }
    };
    auto loadB = [&](int st, int kc) {
        const uint32_t sbase = sb + st * STAGE + BS_OFF;
        const int k0 = kc * BK;
#pragma unroll
        for (int i = 0; i < 2; i++) {
            int idx = tid + i * 256;               // 0..511
            int k = idx >> 4, q = idx & 15;        // 32 rows x 16 chunks of 16B
            size_t go = (size_t)(k0 + k) * A_ + n0 + q * 8;
            cp16(sbase + (uint32_t)(k * B_STRIDE + q * 16), WH + go);
        }
    };

    // prologue: prefetch B chunks 0..2 (one commit-group each)
    ldgA(0);
    loadB(0, 0); cp_commit();
    loadB(1, 1); cp_commit();
    loadB(2, 2); cp_commit();
    cvtA(0);        // A chunk 0 -> stage 0
    ldgA(1);        // prefetch A chunk 1

    // ldmatrix lane addressing
    const uint32_t a_row  = (uint32_t)(warpM * 64 + (lane & 15));
    const uint32_t a_colb = (uint32_t)((lane >> 4) * 16);
    const uint32_t b_krow = (uint32_t)(((lane >> 3) & 1) * 8 + (lane & 7));
    const uint32_t b_colb = (uint32_t)((warpN * 32 + (lane >> 4) * 8) * 2);

    for (int c = 0; c < NKCH; ++c) {
        // groups committed so far cover chunks 0..c+2; wait2 -> chunk c done
        cp_wait2();
        __syncthreads();     // A-stage c visibility (STS in iter c-1) + WAR
        if (c + 3 < NKCH) loadB((c + 3) % NSTAGE, c + 3);
        cp_commit();
        if (c + 1 < NKCH) cvtA((c + 1) % NSTAGE);   // abuf holds chunk c+1
        if (c + 2 < NKCH) ldgA(c + 2);              // refill abuf

        const uint32_t sbase = sb + (c % NSTAGE) * STAGE;
#pragma unroll
        for (int kk = 0; kk < BK; kk += 16) {
            uint32_t aF[4][4], bF[2][4];
#pragma unroll
            for (int mf = 0; mf < 4; mf++) {
                uint32_t ad = sbase + (a_row + mf * 16) * A_STRIDE + kk * 2 + a_colb;
                ldsm_x4(aF[mf], ad);
            }
#pragma unroll
            for (int np = 0; np < 2; np++) {
                uint32_t bdx = sbase + BS_OFF + (b_krow + kk) * B_STRIDE + b_colb + np * 32;
                ldsm_x4_t(bF[np], bdx);
            }
#pragma unroll
            for (int mf = 0; mf < 4; mf++)
#pragma unroll
                for (int nt = 0; nt < 4; nt++) {
                    const int np = nt >> 1, hh = (nt & 1) * 2;
                    mma_fp16(acc[mf][nt], aF[mf], bF[np][hh], bF[np][hh + 1]);
                }
        }
    }

    // ---- fused score epilogue (deterministic partials) ----
    float* spart = (float*)smem;   // stage smem free now
    __syncthreads();

#pragma unroll
    for (int mf = 0; mf < 4; mf++)
#pragma unroll
        for (int h = 0; h < 2; h++) {
            const int row = warpM * 64 + mf * 16 + (lane >> 2) + h * 8;
            const float* sm = (row >= rowsplit) ? sum1 : sum0;
            float s = 0.f;
#pragma unroll
            for (int nf = 0; nf < 4; nf++)
#pragma unroll
                for (int j = 0; j < 2; j++) {
                    const int col = warpN * 32 + nf * 8 + (lane & 3) * 2 + j;
                    float v = acc[mf][nf][h * 2 + j] + sm[col];
                    s += fmaxf(v, 0.f) * swf[col];
                }
            s += __shfl_xor_sync(0xffffffffu, s, 1);
            s += __shfl_xor_sync(0xffffffffu, s, 2);
            if ((lane & 3) == 0) spart[warpN * 128 + row] = s;
        }
    __syncthreads();
    if (tid < 128) {
        float s = spart[tid] + spart[128 + tid] + spart[256 + tid] + spart[384 + tid];
        part[(size_t)blockIdx.x * M_ + m0 + tid] = s;
    }
}

// ---------------------------------------------------------------------------
// Kernel E: weighted sum with FUSED softmax (round-14 proven).
// grid=(4, 128, 4) z = p-quarter (49 pixels); block=128.
// ---------------------------------------------------------------------------
#define PSPLIT 4
#define PCHUNK 49            // 196 / 4

__global__ void weighted_kernel(const float* __restrict__ part,
                                const float* __restrict__ enc,
                                float* __restrict__ alpha_out,
                                float* __restrict__ wpart) {
    __shared__ float al[P_];
    __shared__ float red[128];
    const int b   = blockIdx.y;
    const int z   = blockIdx.z;
    const int tid = threadIdx.x;

    // ---- in-block softmax over P=196 (deterministic, same in all blocks) ----
    const int m0i = b * P_ + tid;
    float v0 = part[m0i] + part[M_ + m0i] + part[2 * M_ + m0i] + part[3 * M_ + m0i];
    float v1 = -INFINITY;
    if (tid + 128 < P_) {
        const int m1i = m0i + 128;
        v1 = part[m1i] + part[M_ + m1i] + part[2 * M_ + m1i] + part[3 * M_ + m1i];
    }
    red[tid] = fmaxf(v0, v1);
    __syncthreads();
#pragma unroll
    for (int s = 64; s; s >>= 1) {
        if (tid < s) red[tid] = fmaxf(red[tid], red[tid + s]);
        __syncthreads();
    }
    const float mx = red[0];
    __syncthreads();
    float e0 = expf(v0 - mx);
    float e1 = (tid + 128 < P_) ? expf(v1 - mx) : 0.f;
    red[tid] = e0 + e1;
    __syncthreads();
#pragma unroll
    for (int s = 64; s; s >>= 1) {
        if (tid < s) red[tid] += red[tid + s];
        __syncthreads();
    }
    const float inv = 1.f / red[0];
    al[tid] = e0 * inv;
    if (tid + 128 < P_) al[tid + 128] = e1 * inv;
    __syncthreads();

    if (blockIdx.x == 0 && z == 0) {
        alpha_out[b * P_ + tid] = al[tid];
        if (tid + 128 < P_) alpha_out[b * P_ + tid + 128] = al[tid + 128];
    }

    // ---- weighted partial sum over this p-quarter ----
    const int p0 = z * PCHUNK;
    const int e4 = blockIdx.x * 128 + tid;
    const float4* base = (const float4*)(enc + ((size_t)b * P_ + p0) * E_) + e4;
    float4 acc = make_float4(0.f, 0.f, 0.f, 0.f);
#pragma unroll 7
    for (int p = 0; p < PCHUNK; p++) {
        float4 v = __ldg(base + (size_t)p * (E_ / 4));
        float a = al[p0 + p];
        acc.x = fmaf(v.x, a, acc.x);
        acc.y = fmaf(v.y, a, acc.y);
        acc.z = fmaf(v.z, a, acc.z);
        acc.w = fmaf(v.w, a, acc.w);
    }
    ((float4*)(wpart + ((size_t)z * B_ + b) * E_))[e4] = acc;
}

// Kernel F: combine 4 p-partials -> awe.  grid=256, block=256 (float4 each)
__global__ void wcombine_kernel(const float* __restrict__ wpart,
                                float* __restrict__ out) {
    const int i = blockIdx.x * 256 + threadIdx.x;     // float4 idx, B_*E_/4
    const float4* p0 = (const float4*)wpart;
    const float4* p1 = p0 + (size_t)B_ * E_ / 4;
    const float4* p2 = p1 + (size_t)B_ * E_ / 4;
    const float4* p3 = p2 + (size_t)B_ * E_ / 4;
    float4 a = p0[i], b = p1[i], c = p2[i], d = p3[i];
    float4 r;
    r.x = (a.x + b.x) + (c.x + d.x);
    r.y = (a.y + b.y) + (c.y + d.y);
    r.z = (a.z + b.z) + (c.z + d.z);
    r.w = (a.w + b.w) + (c.w + d.w);
    ((float4*)out)[i] = r;
}

// ---------------------------------------------------------------------------
// Launch.  Inputs: encoder_out, decoder_hidden, W_enc, b_enc, W_dec, b_dec,
//                  W_full, b_full.   Output: [awe 128*2048][alpha 128*196]
// ---------------------------------------------------------------------------
extern "C" void kernel_launch(void* const* d_in, const int* in_sizes, int n_in,
                              void* d_out, int out_size) {
    const float* enc   = (const float*)d_in[0];
    const float* dh    = (const float*)d_in[1];
    const float* W_enc = (const float*)d_in[2];
    const float* b_enc = (const float*)d_in[3];
    const float* W_dec = (const float*)d_in[4];
    const float* b_dec = (const float*)d_in[5];
    const float* W_ful = (const float*)d_in[6];

    float* out   = (float*)d_out;
    float* awe   = out;
    float* alpha = out + (size_t)B_ * E_;

    __half* WH;
    float *att2p, *part, *wpart;
    cudaGetSymbolAddress((void**)&WH,     g_WH);
    cudaGetSymbolAddress((void**)&att2p,  g_att2p);
    cudaGetSymbolAddress((void**)&part,   g_part);
    cudaGetSymbolAddress((void**)&wpart,  g_wpart);

    cudaFuncSetAttribute(gemm_score_kernel,
                         cudaFuncAttributeMaxDynamicSharedMemorySize, SMEM_TOT);

    // 1. round W_enc to fp16
    round_kernel<<<(E_ * A_ / 4 + 255) / 256, 256>>>(W_enc, WH, E_ * A_ / 4);

    // 2. att2 partials (2-D split: 128 CTAs, 32MB W_dec traffic)
    att2_kernel<<<dim3(B_ / A2GB, DSPLIT), A_>>>(dh, W_dec, att2p);

    // 3. tensor-core GEMM (fused A-convert, BK=32, 4-stage) + score partials
    gemm_score_kernel<<<dim3(4, 196), 256, SMEM_TOT>>>(
        enc, WH, b_enc, att2p, b_dec, W_ful, part);

    // 4. weighted encoding with fused softmax (p-split x4) + combine
    weighted_kernel<<<dim3(4, B_, PSPLIT), 128>>>(part, enc, alpha, wpart);
    wcombine_kernel<<<B_ * E_ / 4 / 256, 256>>>(wpart, awe);
}